// round 5
// baseline (speedup 1.0000x reference)
#include <cuda_runtime.h>
#include <cstdint>

#define NU 100000
#define NI 50000
#define NE 1000000
#define EMB 64
#define DV 16   // float4 chunks per row

// ---------------------------------------------------------------------------
// __device__ scratch (zero-initialized at module load; no allocations)
// ---------------------------------------------------------------------------
__device__ float g_u1[NU * EMB];
__device__ float g_i1[NI * EMB];
__device__ int   g_degU[NU];    // invariant: zero at kernel_launch entry
__device__ int   g_degI[NI];    // (restored by build_csr each call)
__device__ int   g_offU[NU + 1];
__device__ int   g_offI[NI + 1];
__device__ int   g_curU[NU];
__device__ int   g_curI[NI];
__device__ float g_invU[NU];
__device__ float g_invI[NI];
__device__ int   g_csrU[NE];    // per-user neighbor (item) lists
__device__ int   g_csrI[NE];    // per-item neighbor (user) lists

// ---------------------------------------------------------------------------
// (0) degrees: 4 edges per thread via int4
// ---------------------------------------------------------------------------
__global__ void degree_kernel(const int4* __restrict__ es4,
                              const int4* __restrict__ ed4) {
    int t = blockIdx.x * blockDim.x + threadIdx.x;
    if (t < NE / 4) {
        int4 s = __ldg(&es4[t]);
        int4 d = __ldg(&ed4[t]);
        atomicAdd(&g_degU[s.x], 1); atomicAdd(&g_degU[s.y], 1);
        atomicAdd(&g_degU[s.z], 1); atomicAdd(&g_degU[s.w], 1);
        atomicAdd(&g_degI[d.x], 1); atomicAdd(&g_degI[d.y], 1);
        atomicAdd(&g_degI[d.z], 1); atomicAdd(&g_degI[d.w], 1);
    }
}

// ---------------------------------------------------------------------------
// (1) exclusive scan of degrees -> offsets, cursors, inv_deg.
//     Block 0: users, Block 1: items. 1024 threads, chunked, int4 loads.
// ---------------------------------------------------------------------------
__global__ void scan_kernel() {
    __shared__ int ssum[1024];
    const int which = blockIdx.x;
    const int n     = which ? NI : NU;          // both divisible by 4
    int*   deg = which ? g_degI : g_degU;
    int*   off = which ? g_offI : g_offU;
    int*   cur = which ? g_curI : g_curU;
    float* inv = which ? g_invI : g_invU;

    int t = threadIdx.x;
    int chunk = ((((n + 1023) >> 10) + 3) & ~3);   // multiple of 4
    int lo = t * chunk;
    int hi = min(lo + chunk, n);

    int sum = 0;
    const int4* deg4 = reinterpret_cast<const int4*>(deg);
    for (int i = lo; i + 4 <= hi; i += 4) {
        int4 v = deg4[i >> 2];
        sum += v.x + v.y + v.z + v.w;
    }
    ssum[t] = sum;
    __syncthreads();

    for (int s = 1; s < 1024; s <<= 1) {
        int other = (t >= s) ? ssum[t - s] : 0;
        __syncthreads();
        ssum[t] += other;
        __syncthreads();
    }
    int prefix = ssum[t] - sum;

    for (int i = lo; i + 4 <= hi; i += 4) {
        int4 v = deg4[i >> 2];
        int d0 = v.x, d1 = v.y, d2 = v.z, d3 = v.w;
        off[i + 0] = prefix;              cur[i + 0] = prefix;
        inv[i + 0] = d0 ? 1.0f / d0 : 0.f; prefix += d0;
        off[i + 1] = prefix;              cur[i + 1] = prefix;
        inv[i + 1] = d1 ? 1.0f / d1 : 0.f; prefix += d1;
        off[i + 2] = prefix;              cur[i + 2] = prefix;
        inv[i + 2] = d2 ? 1.0f / d2 : 0.f; prefix += d2;
        off[i + 3] = prefix;              cur[i + 3] = prefix;
        inv[i + 3] = d3 ? 1.0f / d3 : 0.f; prefix += d3;
    }
    if (t == 1023) off[n] = prefix;
}

// ---------------------------------------------------------------------------
// (2) build CSR (4 edges/thread) + restore deg=0 invariant for next call
// ---------------------------------------------------------------------------
__global__ void build_csr(const int4* __restrict__ es4,
                          const int4* __restrict__ ed4) {
    int t = blockIdx.x * blockDim.x + threadIdx.x;
    int stride = gridDim.x * blockDim.x;
    // deg consumed by scan already; zero for the next call
    for (int i = t; i < NU + NI; i += stride) {
        if (i < NU) g_degU[i] = 0;
        else        g_degI[i - NU] = 0;
    }
    if (t < NE / 4) {
        int4 s = __ldg(&es4[t]);
        int4 d = __ldg(&ed4[t]);
        g_csrI[atomicAdd(&g_curI[d.x], 1)] = s.x;
        g_csrI[atomicAdd(&g_curI[d.y], 1)] = s.y;
        g_csrI[atomicAdd(&g_curI[d.z], 1)] = s.z;
        g_csrI[atomicAdd(&g_curI[d.w], 1)] = s.w;
        g_csrU[atomicAdd(&g_curU[s.x], 1)] = d.x;
        g_csrU[atomicAdd(&g_curU[s.y], 1)] = d.y;
        g_csrU[atomicAdd(&g_curU[s.z], 1)] = d.z;
        g_csrU[atomicAdd(&g_curU[s.w], 1)] = d.w;
    }
}

// ---------------------------------------------------------------------------
// (3)/(4) fused round: one WARP per output row.
//   lane = c + 16*h : chunk c (float4) of the row, neighbor stream h (0/1).
//   Half h walks CSR slots off+h, off+h+2, ... (stride 2), unroll 4
//   -> 8 neighbor rows in flight per warp per iteration.
//   Halves combined with shfl_xor(16); h=0 half stores the 256B row.
// ---------------------------------------------------------------------------
__global__ void __launch_bounds__(256)
round_kernel(const float4* __restrict__ uin,
             const float4* __restrict__ iin,
             const float*  __restrict__ usw,
             const float*  __restrict__ isw,
             float4* __restrict__ uout,
             float4* __restrict__ iout) {
    int warpId = (blockIdx.x * blockDim.x + threadIdx.x) >> 5;
    int lane   = threadIdx.x & 31;
    int c      = lane & 15;
    int h      = lane >> 4;
    if (warpId >= NI + NU) return;

    const float4* src;
    const int*    adj;
    int off, end, outIdx;
    float inv, sw;
    float4 x;
    float4* outp;

    if (warpId < NI) {                 // item row: pull user rows
        int r = warpId;
        off = g_offI[r]; end = g_offI[r + 1];
        src = uin; adj = g_csrI;
        inv = g_invI[r]; sw = isw[r];
        outIdx = r * DV + c;
        x = iin[outIdx];
        outp = iout;
    } else {                           // user row: pull item rows
        int r = warpId - NI;
        off = g_offU[r]; end = g_offU[r + 1];
        src = iin; adj = g_csrU;
        inv = g_invU[r]; sw = usw[r];
        outIdx = r * DV + c;
        x = uin[outIdx];
        outp = uout;
    }

    float4 acc = make_float4(0.f, 0.f, 0.f, 0.f);
    int k = off + h;
    for (; k + 6 < end; k += 8) {
        int s0 = __ldg(&adj[k    ]);
        int s1 = __ldg(&adj[k + 2]);
        int s2 = __ldg(&adj[k + 4]);
        int s3 = __ldg(&adj[k + 6]);
        float4 a = src[s0 * DV + c];
        float4 b = src[s1 * DV + c];
        float4 d = src[s2 * DV + c];
        float4 e = src[s3 * DV + c];
        acc.x += (a.x + b.x) + (d.x + e.x);
        acc.y += (a.y + b.y) + (d.y + e.y);
        acc.z += (a.z + b.z) + (d.z + e.z);
        acc.w += (a.w + b.w) + (d.w + e.w);
    }
    for (; k < end; k += 2) {
        float4 a = src[__ldg(&adj[k]) * DV + c];
        acc.x += a.x; acc.y += a.y; acc.z += a.z; acc.w += a.w;
    }

    // combine the two neighbor streams
    acc.x += __shfl_xor_sync(0xffffffffu, acc.x, 16);
    acc.y += __shfl_xor_sync(0xffffffffu, acc.y, 16);
    acc.z += __shfl_xor_sync(0xffffffffu, acc.z, 16);
    acc.w += __shfl_xor_sync(0xffffffffu, acc.w, 16);

    if (h == 0) {
        float4 r;
        r.x = acc.x * inv + x.x * sw;
        r.y = acc.y * inv + x.y * sw;
        r.z = acc.z * inv + x.z * sw;
        r.w = acc.w * inv + x.w * sw;
        outp[outIdx] = r;
    }
}

// ---------------------------------------------------------------------------
// Launch: degree(0), scan(1), build(2), round1(3)<-profiled, round2(4)
// ---------------------------------------------------------------------------
extern "C" void kernel_launch(void* const* d_in, const int* in_sizes, int n_in,
                              void* d_out, int out_size) {
    const float* user_emb = (const float*)d_in[0];
    const float* item_emb = (const float*)d_in[1];
    const float* u_sw     = (const float*)d_in[2];
    const float* i_sw     = (const float*)d_in[3];
    const int*   e_src    = (const int*)d_in[4];
    const int*   e_dst    = (const int*)d_in[5];

    float* out_u = (float*)d_out;
    float* out_i = (float*)d_out + (int64_t)NU * EMB;

    void* p;
    cudaGetSymbolAddress(&p, g_u1); float4* u1p = (float4*)p;
    cudaGetSymbolAddress(&p, g_i1); float4* i1p = (float4*)p;

    const int TPB = 256;
    const int eThreads = NE / 4;

    degree_kernel<<<(eThreads + TPB - 1) / TPB, TPB>>>(
        (const int4*)e_src, (const int4*)e_dst);

    scan_kernel<<<2, 1024>>>();

    build_csr<<<(eThreads + TPB - 1) / TPB, TPB>>>(
        (const int4*)e_src, (const int4*)e_dst);

    int rows = NI + NU;
    int rblocks = (rows * 32 + TPB - 1) / TPB;

    round_kernel<<<rblocks, TPB>>>((const float4*)user_emb,
                                   (const float4*)item_emb,
                                   u_sw, i_sw, u1p, i1p);

    round_kernel<<<rblocks, TPB>>>((const float4*)u1p,
                                   (const float4*)i1p,
                                   u_sw, i_sw,
                                   (float4*)out_u, (float4*)out_i);
}

// round 6
// speedup vs baseline: 2.1414x; 2.1414x over previous
#include <cuda_runtime.h>
#include <cstdint>

#define NU 100000
#define NI 50000
#define NE 1000000
#define EMB 64
#define DV 16            // float4 chunks per row

#define TILE 1024        // scan tile (elements per block)
#define NBU ((NU + TILE - 1) / TILE)   // 98
#define NBI ((NI + TILE - 1) / TILE)   // 49

// ---------------------------------------------------------------------------
// __device__ scratch (zero-initialized at module load; no allocations)
// ---------------------------------------------------------------------------
__device__ float g_u1[NU * EMB];
__device__ float g_i1[NI * EMB];
__device__ int   g_degU[NU];        // invariant: zero at kernel_launch entry
__device__ int   g_degI[NI];        // (restored by build_csr each call)
__device__ int   g_offU[NU + 1];
__device__ int   g_offI[NI + 1];
__device__ int   g_curU[NU];
__device__ int   g_curI[NI];
__device__ float g_invU[NU];
__device__ float g_invI[NI];
__device__ int   g_csrU[NE];
__device__ int   g_csrI[NE];
__device__ int   g_partU[NBU];      // per-tile degree sums
__device__ int   g_partI[NBI];
__device__ int   g_baseU[NBU];      // exclusive prefix of tile sums
__device__ int   g_baseI[NBI];

// ---------------------------------------------------------------------------
// (0) degrees: 4 edges per thread via int4
// ---------------------------------------------------------------------------
__global__ void degree_kernel(const int4* __restrict__ es4,
                              const int4* __restrict__ ed4) {
    int t = blockIdx.x * blockDim.x + threadIdx.x;
    if (t < NE / 4) {
        int4 s = __ldg(&es4[t]);
        int4 d = __ldg(&ed4[t]);
        atomicAdd(&g_degU[s.x], 1); atomicAdd(&g_degU[s.y], 1);
        atomicAdd(&g_degU[s.z], 1); atomicAdd(&g_degU[s.w], 1);
        atomicAdd(&g_degI[d.x], 1); atomicAdd(&g_degI[d.y], 1);
        atomicAdd(&g_degI[d.z], 1); atomicAdd(&g_degI[d.w], 1);
    }
}

// ---------------------------------------------------------------------------
// (1) per-tile partial sums. Blocks [0,NBU) -> users, [NBU,NBU+NBI) -> items.
//     256 threads/block, each thread sums one int4 (NU%4==0, NI%4==0).
// ---------------------------------------------------------------------------
__global__ void __launch_bounds__(256)
scan_partials() {
    __shared__ int ssum[256];
    int b = blockIdx.x;
    bool isU = (b < NBU);
    int tileIdx = isU ? b : b - NBU;
    int n       = isU ? NU : NI;
    const int4* deg4 = reinterpret_cast<const int4*>(isU ? g_degU : g_degI);
    int* part = isU ? g_partU : g_partI;

    int i4 = tileIdx * (TILE / 4) + threadIdx.x;   // int4 index
    int s = 0;
    if (i4 * 4 < n) {
        int4 v = deg4[i4];
        s = v.x + v.y + v.z + v.w;
    }
    ssum[threadIdx.x] = s;
    __syncthreads();
    for (int st = 128; st > 0; st >>= 1) {
        if (threadIdx.x < st) ssum[threadIdx.x] += ssum[threadIdx.x + st];
        __syncthreads();
    }
    if (threadIdx.x == 0) part[tileIdx] = ssum[0];
}

// ---------------------------------------------------------------------------
// (2) scan the (147) tile sums. One block; tiny.
// ---------------------------------------------------------------------------
__global__ void __launch_bounds__(256)
scan_bases() {
    __shared__ int sp[NBU + NBI];
    int t = threadIdx.x;
    if (t < NBU)       sp[t]       = g_partU[t];
    if (t < NBI)       sp[NBU + t] = g_partI[t];
    __syncthreads();
    if (t == 0) {
        int acc = 0;
        for (int i = 0; i < NBU; i++) { int v = sp[i]; sp[i] = acc; acc += v; }
        g_offU[NU] = acc;
        acc = 0;
        for (int i = 0; i < NBI; i++) { int v = sp[NBU + i]; sp[NBU + i] = acc; acc += v; }
        g_offI[NI] = acc;
    }
    __syncthreads();
    if (t < NBU) g_baseU[t] = sp[t];
    if (t < NBI) g_baseI[t] = sp[NBU + t];
}

// ---------------------------------------------------------------------------
// (3) per-tile local exclusive scan + base -> off/cur/inv.
//     Same grid shape as scan_partials. Each thread owns 4 elements.
// ---------------------------------------------------------------------------
__global__ void __launch_bounds__(256)
scan_finish() {
    __shared__ int ssum[256];
    int b = blockIdx.x;
    bool isU = (b < NBU);
    int tileIdx = isU ? b : b - NBU;
    int n       = isU ? NU : NI;
    int* deg   = isU ? g_degU : g_degI;
    int* off   = isU ? g_offU : g_offI;
    int* cur   = isU ? g_curU : g_curI;
    float* inv = isU ? g_invU : g_invI;
    int base   = isU ? g_baseU[tileIdx] : g_baseI[tileIdx];

    int t = threadIdx.x;
    int i4 = tileIdx * (TILE / 4) + t;
    int e0 = i4 * 4;
    int4 v = make_int4(0, 0, 0, 0);
    bool act = (e0 < n);
    if (act) v = reinterpret_cast<const int4*>(deg)[i4];
    int s = v.x + v.y + v.z + v.w;

    ssum[t] = s;
    __syncthreads();
    // Hillis-Steele inclusive over 256 thread sums
    for (int st = 1; st < 256; st <<= 1) {
        int o = (t >= st) ? ssum[t - st] : 0;
        __syncthreads();
        ssum[t] += o;
        __syncthreads();
    }
    int pfx = base + ssum[t] - s;   // exclusive prefix for this thread's 4 elems

    if (act) {
        off[e0 + 0] = pfx;               cur[e0 + 0] = pfx;
        inv[e0 + 0] = v.x ? 1.0f / v.x : 0.f;  pfx += v.x;
        off[e0 + 1] = pfx;               cur[e0 + 1] = pfx;
        inv[e0 + 1] = v.y ? 1.0f / v.y : 0.f;  pfx += v.y;
        off[e0 + 2] = pfx;               cur[e0 + 2] = pfx;
        inv[e0 + 2] = v.z ? 1.0f / v.z : 0.f;  pfx += v.z;
        off[e0 + 3] = pfx;               cur[e0 + 3] = pfx;
        inv[e0 + 3] = v.w ? 1.0f / v.w : 0.f;
    }
}

// ---------------------------------------------------------------------------
// (4) build CSR (4 edges/thread) + restore deg=0 invariant for next call
// ---------------------------------------------------------------------------
__global__ void build_csr(const int4* __restrict__ es4,
                          const int4* __restrict__ ed4) {
    int t = blockIdx.x * blockDim.x + threadIdx.x;
    int stride = gridDim.x * blockDim.x;
    for (int i = t; i < NU + NI; i += stride) {
        if (i < NU) g_degU[i] = 0;
        else        g_degI[i - NU] = 0;
    }
    if (t < NE / 4) {
        int4 s = __ldg(&es4[t]);
        int4 d = __ldg(&ed4[t]);
        g_csrI[atomicAdd(&g_curI[d.x], 1)] = s.x;
        g_csrI[atomicAdd(&g_curI[d.y], 1)] = s.y;
        g_csrI[atomicAdd(&g_curI[d.z], 1)] = s.z;
        g_csrI[atomicAdd(&g_curI[d.w], 1)] = s.w;
        g_csrU[atomicAdd(&g_curU[s.x], 1)] = d.x;
        g_csrU[atomicAdd(&g_curU[s.y], 1)] = d.y;
        g_csrU[atomicAdd(&g_curU[s.z], 1)] = d.z;
        g_csrU[atomicAdd(&g_curU[s.w], 1)] = d.w;
    }
}

// ---------------------------------------------------------------------------
// (5)/(6) fused round: one WARP per output row (unchanged from R5 — 57.8µs).
// ---------------------------------------------------------------------------
__global__ void __launch_bounds__(256)
round_kernel(const float4* __restrict__ uin,
             const float4* __restrict__ iin,
             const float*  __restrict__ usw,
             const float*  __restrict__ isw,
             float4* __restrict__ uout,
             float4* __restrict__ iout) {
    int warpId = (blockIdx.x * blockDim.x + threadIdx.x) >> 5;
    int lane   = threadIdx.x & 31;
    int c      = lane & 15;
    int h      = lane >> 4;
    if (warpId >= NI + NU) return;

    const float4* src;
    const int*    adj;
    int off, end, outIdx;
    float inv, sw;
    float4 x;
    float4* outp;

    if (warpId < NI) {
        int r = warpId;
        off = g_offI[r]; end = g_offI[r + 1];
        src = uin; adj = g_csrI;
        inv = g_invI[r]; sw = isw[r];
        outIdx = r * DV + c;
        x = iin[outIdx];
        outp = iout;
    } else {
        int r = warpId - NI;
        off = g_offU[r]; end = g_offU[r + 1];
        src = iin; adj = g_csrU;
        inv = g_invU[r]; sw = usw[r];
        outIdx = r * DV + c;
        x = uin[outIdx];
        outp = uout;
    }

    float4 acc = make_float4(0.f, 0.f, 0.f, 0.f);
    int k = off + h;
    for (; k + 6 < end; k += 8) {
        int s0 = __ldg(&adj[k    ]);
        int s1 = __ldg(&adj[k + 2]);
        int s2 = __ldg(&adj[k + 4]);
        int s3 = __ldg(&adj[k + 6]);
        float4 a = src[s0 * DV + c];
        float4 b = src[s1 * DV + c];
        float4 d = src[s2 * DV + c];
        float4 e = src[s3 * DV + c];
        acc.x += (a.x + b.x) + (d.x + e.x);
        acc.y += (a.y + b.y) + (d.y + e.y);
        acc.z += (a.z + b.z) + (d.z + e.z);
        acc.w += (a.w + b.w) + (d.w + e.w);
    }
    for (; k < end; k += 2) {
        float4 a = src[__ldg(&adj[k]) * DV + c];
        acc.x += a.x; acc.y += a.y; acc.z += a.z; acc.w += a.w;
    }

    acc.x += __shfl_xor_sync(0xffffffffu, acc.x, 16);
    acc.y += __shfl_xor_sync(0xffffffffu, acc.y, 16);
    acc.z += __shfl_xor_sync(0xffffffffu, acc.z, 16);
    acc.w += __shfl_xor_sync(0xffffffffu, acc.w, 16);

    if (h == 0) {
        float4 r;
        r.x = acc.x * inv + x.x * sw;
        r.y = acc.y * inv + x.y * sw;
        r.z = acc.z * inv + x.z * sw;
        r.w = acc.w * inv + x.w * sw;
        outp[outIdx] = r;
    }
}

// ---------------------------------------------------------------------------
// Launch: degree(0), partials(1), bases(2), finish(3), build(4),
//         round1(5) <- ncu -s 5 captures this, round2(6)
// ---------------------------------------------------------------------------
extern "C" void kernel_launch(void* const* d_in, const int* in_sizes, int n_in,
                              void* d_out, int out_size) {
    const float* user_emb = (const float*)d_in[0];
    const float* item_emb = (const float*)d_in[1];
    const float* u_sw     = (const float*)d_in[2];
    const float* i_sw     = (const float*)d_in[3];
    const int*   e_src    = (const int*)d_in[4];
    const int*   e_dst    = (const int*)d_in[5];

    float* out_u = (float*)d_out;
    float* out_i = (float*)d_out + (int64_t)NU * EMB;

    void* p;
    cudaGetSymbolAddress(&p, g_u1); float4* u1p = (float4*)p;
    cudaGetSymbolAddress(&p, g_i1); float4* i1p = (float4*)p;

    const int TPB = 256;
    const int eThreads = NE / 4;

    degree_kernel<<<(eThreads + TPB - 1) / TPB, TPB>>>(
        (const int4*)e_src, (const int4*)e_dst);

    scan_partials<<<NBU + NBI, 256>>>();
    scan_bases<<<1, 256>>>();
    scan_finish<<<NBU + NBI, 256>>>();

    build_csr<<<(eThreads + TPB - 1) / TPB, TPB>>>(
        (const int4*)e_src, (const int4*)e_dst);

    int rows = NI + NU;
    int rblocks = (rows * 32 + TPB - 1) / TPB;

    round_kernel<<<rblocks, TPB>>>((const float4*)user_emb,
                                   (const float4*)item_emb,
                                   u_sw, i_sw, u1p, i1p);

    round_kernel<<<rblocks, TPB>>>((const float4*)u1p,
                                   (const float4*)i1p,
                                   u_sw, i_sw,
                                   (float4*)out_u, (float4*)out_i);
}